// round 1
// baseline (speedup 1.0000x reference)
#include <cuda_runtime.h>
#include <math.h>

// Problem constants
#define VOX 131072          // B*D*H*W = 4*32*32*32
#define CCH 136             // C
#define PCH 408             // P = 3*C
#define NO  135             // C-1
#define NTAP 7

// Scratch (device globals — no cudaMalloc allowed)
__device__ float g_p [(size_t)VOX * PCH];   // conv output (post-relu)
__device__ float g_h [(size_t)VOX * PCH];   // fc1 output (post-relu)
__device__ float g_wc [NTAP * CCH * PCH];   // compacted conv weights, [k= off*136+c][o]
__device__ float g_w1t[PCH * PCH];          // w1 transposed: [k][o]
__device__ float g_w2t[PCH * 136];          // w2 transposed + padded to 136 cols: [k][j]

// 7-point stencil taps inside the 3x3x3 kernel (kd*9+kh*3+kw), and their
// spatial offsets (kd-1, kh-1, kw-1). conv_general_dilated = cross-correlation.
__constant__ int c_tap[NTAP] = {4, 10, 12, 13, 14, 16, 22};
__constant__ int c_dz[NTAP]  = {-1, 0, 0, 0, 0, 0, 1};
__constant__ int c_dy[NTAP]  = { 0,-1, 0, 0, 0, 1, 0};
__constant__ int c_dx[NTAP]  = { 0, 0,-1, 0, 1, 0, 0};

// ---------------- weight repack kernels ----------------
__global__ void k_prep_wc(const float* __restrict__ wp) {
    int i = blockIdx.x * 256 + threadIdx.x;           // NTAP*CCH*PCH
    if (i >= NTAP * CCH * PCH) return;
    int o   = i % PCH;
    int rem = i / PCH;
    int c   = rem % CCH;
    int off = rem / CCH;
    g_wc[i] = wp[((size_t)o * CCH + c) * 27 + c_tap[off]];
}

__global__ void k_prep_w1t(const float* __restrict__ w1) {
    int i = blockIdx.x * 256 + threadIdx.x;           // PCH*PCH
    if (i >= PCH * PCH) return;
    int n = i % PCH, k = i / PCH;
    g_w1t[i] = w1[n * PCH + k];
}

__global__ void k_prep_w2t(const float* __restrict__ w2) {
    int i = blockIdx.x * 256 + threadIdx.x;           // PCH*136
    if (i >= PCH * 136) return;
    int n = i % 136, k = i / 136;
    g_w2t[i] = (n < NO) ? w2[n * PCH + k] : 0.f;
}

// ---------------- GEMM 1: conv (gathered A) + relu -> g_p ----------------
// p[v][o] = relu( sum_{off,c} x[neighbor(v,off)][c] * Wc[off*136+c][o] )
// Tile: M=128 voxels, N=64 outputs, K=8; 256 threads, 8x4 accум per thread.
__global__ void __launch_bounds__(256) k_conv(const float* __restrict__ x) {
    __shared__ float As[8][128];
    __shared__ float Bs[8][64];
    const int t = threadIdx.x;
    const int mbase = blockIdx.x * 128;
    const int nbase = blockIdx.y * 64;
    const int tr = t >> 4, tc = t & 15;               // compute mapping
    const int ar = t >> 1, ak = (t & 1) * 4;          // A-load mapping (1 float4/thread)
    const int vm = mbase + ar;
    const int w0 = vm & 31, h0 = (vm >> 5) & 31, d0 = (vm >> 10) & 31, b0 = vm >> 15;
    const int bk = t >> 6, bn = t & 63;               // B-load mapping (2 floats/thread)
    const int n_b = nbase + bn;

    float acc[8][4];
    #pragma unroll
    for (int i = 0; i < 8; i++)
        #pragma unroll
        for (int j = 0; j < 4; j++) acc[i][j] = 0.f;

    for (int kb = 0; kb < 119; kb++) {                // K = 7*136 = 952 = 119*8
        // A: gather 4 consecutive channels of one shifted-neighbor row
        int kg  = kb * 8 + ak;
        int off = kg / 136;
        int c   = kg - off * 136;                     // 4-aligned, chunk stays in one tap
        int dd = d0 + c_dz[off], hh = h0 + c_dy[off], ww = w0 + c_dx[off];
        float4 av = make_float4(0.f, 0.f, 0.f, 0.f);
        if ((((unsigned)dd) | ((unsigned)hh) | ((unsigned)ww)) < 32u) {
            av = *reinterpret_cast<const float4*>(
                x + ((size_t)(((b0 * 32 + dd) * 32 + hh) * 32 + ww)) * CCH + c);
        }
        // B: two rows of compacted weights
        float bv0 = 0.f, bv1 = 0.f;
        if (n_b < PCH) {
            bv0 = g_wc[(kb * 8 + bk    ) * PCH + n_b];
            bv1 = g_wc[(kb * 8 + bk + 4) * PCH + n_b];
        }
        __syncthreads();
        As[ak + 0][ar] = av.x; As[ak + 1][ar] = av.y;
        As[ak + 2][ar] = av.z; As[ak + 3][ar] = av.w;
        Bs[bk][bn] = bv0; Bs[bk + 4][bn] = bv1;
        __syncthreads();
        #pragma unroll
        for (int k = 0; k < 8; k++) {
            float a[8], b[4];
            #pragma unroll
            for (int i = 0; i < 8; i++) a[i] = As[k][tr * 8 + i];
            #pragma unroll
            for (int j = 0; j < 4; j++) b[j] = Bs[k][tc * 4 + j];
            #pragma unroll
            for (int i = 0; i < 8; i++)
                #pragma unroll
                for (int j = 0; j < 4; j++) acc[i][j] = fmaf(a[i], b[j], acc[i][j]);
        }
    }
    const int n0 = nbase + tc * 4;
    if (n0 < PCH) {
        #pragma unroll
        for (int i = 0; i < 8; i++) {
            int row = mbase + tr * 8 + i;
            float4 v;
            v.x = fmaxf(acc[i][0], 0.f);
            v.y = fmaxf(acc[i][1], 0.f);
            v.z = fmaxf(acc[i][2], 0.f);
            v.w = fmaxf(acc[i][3], 0.f);
            *reinterpret_cast<float4*>(&g_p[(size_t)row * PCH + n0]) = v;
        }
    }
}

// ---------------- GEMM 2: h = relu(w1 @ p + b1) -> g_h ----------------
__global__ void __launch_bounds__(256) k_fc1(const float* __restrict__ b1) {
    __shared__ float As[8][128];
    __shared__ float Bs[8][64];
    const int t = threadIdx.x;
    const int mbase = blockIdx.x * 128;
    const int nbase = blockIdx.y * 64;
    const int tr = t >> 4, tc = t & 15;
    const int ar = t >> 1, ak = (t & 1) * 4;
    const int vm = mbase + ar;
    const int bk = t >> 6, bn = t & 63;
    const int n_b = nbase + bn;

    float acc[8][4];
    #pragma unroll
    for (int i = 0; i < 8; i++)
        #pragma unroll
        for (int j = 0; j < 4; j++) acc[i][j] = 0.f;

    for (int kb = 0; kb < 51; kb++) {                 // K = 408 = 51*8
        int kg = kb * 8 + ak;
        float4 av = *reinterpret_cast<const float4*>(&g_p[(size_t)vm * PCH + kg]);
        float bv0 = 0.f, bv1 = 0.f;
        if (n_b < PCH) {
            bv0 = g_w1t[(kb * 8 + bk    ) * PCH + n_b];
            bv1 = g_w1t[(kb * 8 + bk + 4) * PCH + n_b];
        }
        __syncthreads();
        As[ak + 0][ar] = av.x; As[ak + 1][ar] = av.y;
        As[ak + 2][ar] = av.z; As[ak + 3][ar] = av.w;
        Bs[bk][bn] = bv0; Bs[bk + 4][bn] = bv1;
        __syncthreads();
        #pragma unroll
        for (int k = 0; k < 8; k++) {
            float a[8], b[4];
            #pragma unroll
            for (int i = 0; i < 8; i++) a[i] = As[k][tr * 8 + i];
            #pragma unroll
            for (int j = 0; j < 4; j++) b[j] = Bs[k][tc * 4 + j];
            #pragma unroll
            for (int i = 0; i < 8; i++)
                #pragma unroll
                for (int j = 0; j < 4; j++) acc[i][j] = fmaf(a[i], b[j], acc[i][j]);
        }
    }
    const int n0 = nbase + tc * 4;
    if (n0 < PCH) {
        float bb0 = b1[n0], bb1 = b1[n0 + 1], bb2 = b1[n0 + 2], bb3 = b1[n0 + 3];
        #pragma unroll
        for (int i = 0; i < 8; i++) {
            int row = mbase + tr * 8 + i;
            float4 v;
            v.x = fmaxf(acc[i][0] + bb0, 0.f);
            v.y = fmaxf(acc[i][1] + bb1, 0.f);
            v.z = fmaxf(acc[i][2] + bb2, 0.f);
            v.w = fmaxf(acc[i][3] + bb3, 0.f);
            *reinterpret_cast<float4*>(&g_h[(size_t)row * PCH + n0]) = v;
        }
    }
}

// ---------------- GEMM 3: upd = w2 @ h + emb[y]; out = x + mask*tanh(upd) ----------------
__global__ void __launch_bounds__(256) k_fc2(const float* __restrict__ x,
                                             const int*   __restrict__ y,
                                             const float* __restrict__ rmask,
                                             const float* __restrict__ emb,
                                             float*       __restrict__ out) {
    __shared__ float As[8][128];
    __shared__ float Bs[8][64];
    const int t = threadIdx.x;
    const int mbase = blockIdx.x * 128;
    const int nbase = blockIdx.y * 64;
    const int tr = t >> 4, tc = t & 15;
    const int ar = t >> 1, ak = (t & 1) * 4;
    const int vm = mbase + ar;
    const int bk = t >> 6, bn = t & 63;
    const int n_b = nbase + bn;

    float acc[8][4];
    #pragma unroll
    for (int i = 0; i < 8; i++)
        #pragma unroll
        for (int j = 0; j < 4; j++) acc[i][j] = 0.f;

    for (int kb = 0; kb < 51; kb++) {                 // K = 408
        int kg = kb * 8 + ak;
        float4 av = *reinterpret_cast<const float4*>(&g_h[(size_t)vm * PCH + kg]);
        float bv0 = 0.f, bv1 = 0.f;
        if (n_b < 136) {                              // padded col 135 is zero
            bv0 = g_w2t[(kb * 8 + bk    ) * 136 + n_b];
            bv1 = g_w2t[(kb * 8 + bk + 4) * 136 + n_b];
        }
        __syncthreads();
        As[ak + 0][ar] = av.x; As[ak + 1][ar] = av.y;
        As[ak + 2][ar] = av.z; As[ak + 3][ar] = av.w;
        Bs[bk][bn] = bv0; Bs[bk + 4][bn] = bv1;
        __syncthreads();
        #pragma unroll
        for (int k = 0; k < 8; k++) {
            float a[8], b[4];
            #pragma unroll
            for (int i = 0; i < 8; i++) a[i] = As[k][tr * 8 + i];
            #pragma unroll
            for (int j = 0; j < 4; j++) b[j] = Bs[k][tc * 4 + j];
            #pragma unroll
            for (int i = 0; i < 8; i++)
                #pragma unroll
                for (int j = 0; j < 4; j++) acc[i][j] = fmaf(a[i], b[j], acc[i][j]);
        }
    }
    // Epilogue: channel j=n (0..134) maps to output channel 1+n.
    const int n0 = nbase + tc * 4;
    const int bb = mbase >> 15;                       // whole CTA is one batch element
    const int yb = y[bb];
    float e[4];
    #pragma unroll
    for (int j = 0; j < 4; j++)
        e[j] = (n0 + j < NO) ? emb[yb * NO + n0 + j] : 0.f;

    #pragma unroll
    for (int i = 0; i < 8; i++) {
        int v = mbase + tr * 8 + i;
        float gray = x[(size_t)v * CCH];
        float m = (rmask[v] <= 0.5f && gray > 0.1f) ? 1.f : 0.f;
        #pragma unroll
        for (int j = 0; j < 4; j++) {
            int n = n0 + j;
            if (n < NO) {
                float u = acc[i][j] + e[j];
                out[(size_t)v * CCH + 1 + n] =
                    x[(size_t)v * CCH + 1 + n] + m * tanhf(u);
            }
        }
        if (nbase == 0 && tc == 0) out[(size_t)v * CCH] = gray;  // gray passthrough
    }
}

// ---------------- launch ----------------
extern "C" void kernel_launch(void* const* d_in, const int* in_sizes, int n_in,
                              void* d_out, int out_size) {
    const float* x     = (const float*)d_in[0];
    const int*   y     = (const int*)  d_in[1];
    const float* rmask = (const float*)d_in[2];
    const float* wp    = (const float*)d_in[3];
    const float* w1    = (const float*)d_in[4];
    const float* b1    = (const float*)d_in[5];
    const float* w2    = (const float*)d_in[6];
    const float* emb   = (const float*)d_in[7];
    float* out = (float*)d_out;

    k_prep_wc <<<(NTAP * CCH * PCH + 255) / 256, 256>>>(wp);
    k_prep_w1t<<<(PCH * PCH + 255) / 256, 256>>>(w1);
    k_prep_w2t<<<(PCH * 136 + 255) / 256, 256>>>(w2);

    k_conv<<<dim3(VOX / 128, (PCH + 63) / 64), 256>>>(x);        // 1024 x 7
    k_fc1 <<<dim3(VOX / 128, (PCH + 63) / 64), 256>>>(b1);       // 1024 x 7
    k_fc2 <<<dim3(VOX / 128, (NO + 63) / 64), 256>>>(x, y, rmask, emb, out); // 1024 x 3
}

// round 3
// speedup vs baseline: 3.5557x; 3.5557x over previous
#include <cuda_runtime.h>
#include <math.h>
#include <stdint.h>

#define VOX   131072
#define CCH   136
#define PCH   408
#define PP    416          // padded P (13 * 32)
#define NO    135
#define NT_CONV 54         // padded n8-tiles for N=408 (3 blocks * 18)
#define NT_FC2  18
#define K8_CONV 120        // conv K = 952 padded to 960
#define K8_FC   52         // fc K = 408 padded to 416

#define SA_STRIDE 20       // 16 k-floats + 4 pad (conflict-free frag loads)
#define SA_STAGE  (128*SA_STRIDE)   // 2560 floats
#define SB_STAGE  (2*18*64)         // 2304 floats (2 k8-groups x 18 ntiles x 64)

// ---------------- scratch (device globals; no cudaMalloc allowed) ----------------
__device__ float g_p  [(size_t)VOX * PP];                 // conv out (relu, tf32-rounded)
__device__ float g_h  [(size_t)VOX * PP];                 // fc1 out (relu, tf32-rounded)
__device__ float g_wcf[(size_t)K8_CONV * NT_CONV * 64];   // conv W, fragment-major
__device__ float g_w1f[(size_t)K8_FC   * NT_CONV * 64];   // w1^T, fragment-major
__device__ float g_w2f[(size_t)K8_FC   * NT_FC2  * 64];   // w2^T, fragment-major

__constant__ int c_tap[7] = {4,10,12,13,14,16,22};
__constant__ int c_dz[7]  = {-1,0,0,0,0,0,1};
__constant__ int c_dy[7]  = {0,-1,0,0,0,1,0};
__constant__ int c_dx[7]  = {0,0,-1,0,1,0,0};

// ---------------- helpers ----------------
__device__ __forceinline__ float to_tf32(float x){
    uint32_t u; asm("cvt.rna.tf32.f32 %0, %1;" : "=r"(u) : "f"(x));
    return __uint_as_float(u);
}
__device__ __forceinline__ void mma_t(float* c, const uint32_t* a, uint32_t b0, uint32_t b1){
    asm volatile("mma.sync.aligned.m16n8k8.row.col.f32.tf32.tf32.f32 "
                 "{%0,%1,%2,%3}, {%4,%5,%6,%7}, {%8,%9}, {%0,%1,%2,%3};"
                 : "+f"(c[0]), "+f"(c[1]), "+f"(c[2]), "+f"(c[3])
                 : "r"(a[0]), "r"(a[1]), "r"(a[2]), "r"(a[3]), "r"(b0), "r"(b1));
}
__device__ __forceinline__ void cpa(uint32_t d, const void* s, int bytes){
    asm volatile("cp.async.cg.shared.global [%0], [%1], 16, %2;" :: "r"(d), "l"(s), "r"(bytes));
}
__device__ __forceinline__ void cp_commit(){ asm volatile("cp.async.commit_group;"); }
template<int N> __device__ __forceinline__ void cp_wait(){ asm volatile("cp.async.wait_group %0;" :: "n"(N)); }

// one K-stage (16 k) of warp-tile 64x72 compute.
// sA: [128][SA_STRIDE] row-major; sB: [2 k8][18 ntile][32 lane][2 slot].
__device__ __forceinline__ void stage_compute(const float* __restrict__ sA,
                                              const float* __restrict__ sB,
                                              float (&acc)[4][9][4],
                                              int wm, int wn, int gID, int tID, int lane){
    #pragma unroll
    for (int g8 = 0; g8 < 2; g8++){
        uint32_t a[4][4];
        #pragma unroll
        for (int mt = 0; mt < 4; mt++){
            const float* ap = sA + (wm + mt*16 + gID)*SA_STRIDE + g8*8 + tID;
            a[mt][0] = __float_as_uint(ap[0]);
            a[mt][1] = __float_as_uint(ap[8*SA_STRIDE]);
            a[mt][2] = __float_as_uint(ap[4]);
            a[mt][3] = __float_as_uint(ap[8*SA_STRIDE + 4]);
        }
        #pragma unroll
        for (int nt = 0; nt < 9; nt++){
            float2 bv = *reinterpret_cast<const float2*>(sB + (((g8*18) + wn + nt)*32 + lane)*2);
            uint32_t b0 = __float_as_uint(bv.x), b1 = __float_as_uint(bv.y);
            #pragma unroll
            for (int mt = 0; mt < 4; mt++)
                mma_t(acc[mt][nt], a[mt], b0, b1);
        }
    }
}

// ---------------- weight prep: pack fragment-major, tf32-rounded ----------------
__global__ void k_prep_wc(const float* __restrict__ wp){
    int i = blockIdx.x*256 + threadIdx.x;
    if (i >= K8_CONV*NT_CONV*64) return;
    int slot = i & 1, lane = (i>>1)&31, ntile = (i>>6)%NT_CONV, k8 = (i>>6)/NT_CONV;
    int kk = slot*4 + (lane&3);
    int k = k8*8 + kk, n = ntile*8 + (lane>>2);
    float v = 0.f;
    if (k < 952 && n < PCH){
        int off = k/136, c = k - off*136;
        v = to_tf32(wp[((size_t)n*CCH + c)*27 + c_tap[off]]);
    }
    g_wcf[i] = v;
}
__global__ void k_prep_w1(const float* __restrict__ w1){
    int i = blockIdx.x*256 + threadIdx.x;
    if (i >= K8_FC*NT_CONV*64) return;
    int slot = i & 1, lane = (i>>1)&31, ntile = (i>>6)%NT_CONV, k8 = (i>>6)/NT_CONV;
    int k = k8*8 + slot*4 + (lane&3), n = ntile*8 + (lane>>2);
    g_w1f[i] = (k < PCH && n < PCH) ? to_tf32(w1[(size_t)n*PCH + k]) : 0.f;
}
__global__ void k_prep_w2(const float* __restrict__ w2){
    int i = blockIdx.x*256 + threadIdx.x;
    if (i >= K8_FC*NT_FC2*64) return;
    int slot = i & 1, lane = (i>>1)&31, ntile = (i>>6)%NT_FC2, k8 = (i>>6)/NT_FC2;
    int k = k8*8 + slot*4 + (lane&3), n = ntile*8 + (lane>>2);
    g_w2f[i] = (k < PCH && n < NO) ? to_tf32(w2[(size_t)n*PCH + k]) : 0.f;
}

// ---------------- GEMM 1: conv (gathered A) + relu -> g_p ----------------
__global__ void __launch_bounds__(128) k_conv(const float* __restrict__ x){
    __shared__ __align__(16) float sA[2*SA_STAGE];
    __shared__ __align__(16) float sB[2*SB_STAGE];
    const int tid = threadIdx.x;
    const int lane = tid & 31, warp = tid >> 5;
    const int gID = lane >> 2, tID = lane & 3;
    const int wm = (warp & 1) * 64, wn = (warp >> 1) * 9;
    const int mb = blockIdx.x * 128;
    const int nb = blockIdx.y;

    // A-producer: this thread owns voxel row (mb+tid); precompute 7 neighbor ptrs
    const int vm = mb + tid;
    const int w0 = vm & 31, h0 = (vm >> 5) & 31, d0 = (vm >> 10) & 31, bb = vm >> 15;
    const float* nbr[7]; unsigned vmask = 0;
    #pragma unroll
    for (int o = 0; o < 7; o++){
        int dd = d0 + c_dz[o], hh = h0 + c_dy[o], ww = w0 + c_dx[o];
        bool v = ((((unsigned)dd) | ((unsigned)hh)) | ((unsigned)ww)) < 32u;
        nbr[o] = x + (v ? ((size_t)(((bb*32 + dd)*32 + hh)*32 + ww))*CCH : 0);
        if (v) vmask |= 1u << o;
    }
    const uint32_t sAb = (uint32_t)__cvta_generic_to_shared(sA);
    const uint32_t sBb = (uint32_t)__cvta_generic_to_shared(sB);

    auto loadA = [&](int s, int buf){
        uint32_t d = sAb + (uint32_t)(buf*SA_STAGE + tid*SA_STRIDE)*4;
        #pragma unroll
        for (int kc = 0; kc < 4; kc++){
            int k = s*16 + kc*4;
            int off = k/136, c = k - off*136;
            int ok = (off < 7) && ((vmask >> off) & 1);
            cpa(d + kc*16, nbr[off < 7 ? off : 0] + c, ok ? 16 : 0);
        }
    };
    auto loadB = [&](int s, int buf){
        #pragma unroll
        for (int i = 0; i < 5; i++){
            int ci = i*128 + tid;                 // 576 float4 per stage
            if (ci < 576){
                int g = ci/288, r = ci - g*288;
                const float* src = g_wcf + ((size_t)((s*2 + g)*NT_CONV + nb*18))*64 + r*4;
                cpa(sBb + (uint32_t)(buf*SB_STAGE + g*1152 + r*4)*4, src, 16);
            }
        }
    };

    float acc[4][9][4];
    #pragma unroll
    for (int i = 0; i < 4; i++) for (int j = 0; j < 9; j++) for (int q = 0; q < 4; q++) acc[i][j][q] = 0.f;

    loadA(0,0); loadB(0,0); cp_commit();
    const int NS = 60;                            // 120 k8 / 2 per stage
    for (int s = 0; s < NS; s++){
        if (s + 1 < NS){ loadA(s+1,(s+1)&1); loadB(s+1,(s+1)&1); cp_commit(); cp_wait<1>(); }
        else cp_wait<0>();
        __syncthreads();
        stage_compute(sA + (s&1)*SA_STAGE, sB + (s&1)*SB_STAGE, acc, wm, wn, gID, tID, lane);
        if (s + 1 < NS) __syncthreads();
    }
    #pragma unroll
    for (int nt = 0; nt < 9; nt++){
        int cn = nb*144 + (wn + nt)*8 + 2*tID;
        if (cn >= PP) continue;
        #pragma unroll
        for (int mt = 0; mt < 4; mt++){
            int row = mb + wm + mt*16 + gID;
            float2 v0, v1;
            v0.x = (cn   < PCH) ? to_tf32(fmaxf(acc[mt][nt][0], 0.f)) : 0.f;
            v0.y = (cn+1 < PCH) ? to_tf32(fmaxf(acc[mt][nt][1], 0.f)) : 0.f;
            v1.x = (cn   < PCH) ? to_tf32(fmaxf(acc[mt][nt][2], 0.f)) : 0.f;
            v1.y = (cn+1 < PCH) ? to_tf32(fmaxf(acc[mt][nt][3], 0.f)) : 0.f;
            *reinterpret_cast<float2*>(&g_p[(size_t)row*PP + cn])     = v0;
            *reinterpret_cast<float2*>(&g_p[(size_t)(row+8)*PP + cn]) = v1;
        }
    }
}

// ---------------- GEMM 2: h = relu(w1 @ p + b1) -> g_h ----------------
__global__ void __launch_bounds__(128) k_fc1(const float* __restrict__ b1){
    __shared__ __align__(16) float sA[2*SA_STAGE];
    __shared__ __align__(16) float sB[2*SB_STAGE];
    const int tid = threadIdx.x;
    const int lane = tid & 31, warp = tid >> 5;
    const int gID = lane >> 2, tID = lane & 3;
    const int wm = (warp & 1) * 64, wn = (warp >> 1) * 9;
    const int mb = blockIdx.x * 128;
    const int nb = blockIdx.y;

    const uint32_t sAb = (uint32_t)__cvta_generic_to_shared(sA);
    const uint32_t sBb = (uint32_t)__cvta_generic_to_shared(sB);
    const float* arow = g_p + (size_t)(mb + tid)*PP;

    auto loadA = [&](int s, int buf){
        uint32_t d = sAb + (uint32_t)(buf*SA_STAGE + tid*SA_STRIDE)*4;
        const float* src = arow + s*16;
        #pragma unroll
        for (int kc = 0; kc < 4; kc++) cpa(d + kc*16, src + kc*4, 16);
    };
    auto loadB = [&](int s, int buf){
        #pragma unroll
        for (int i = 0; i < 5; i++){
            int ci = i*128 + tid;
            if (ci < 576){
                int g = ci/288, r = ci - g*288;
                const float* src = g_w1f + ((size_t)((s*2 + g)*NT_CONV + nb*18))*64 + r*4;
                cpa(sBb + (uint32_t)(buf*SB_STAGE + g*1152 + r*4)*4, src, 16);
            }
        }
    };

    float acc[4][9][4];
    #pragma unroll
    for (int i = 0; i < 4; i++) for (int j = 0; j < 9; j++) for (int q = 0; q < 4; q++) acc[i][j][q] = 0.f;

    loadA(0,0); loadB(0,0); cp_commit();
    const int NS = 26;                            // 52 k8 / 2
    for (int s = 0; s < NS; s++){
        if (s + 1 < NS){ loadA(s+1,(s+1)&1); loadB(s+1,(s+1)&1); cp_commit(); cp_wait<1>(); }
        else cp_wait<0>();
        __syncthreads();
        stage_compute(sA + (s&1)*SA_STAGE, sB + (s&1)*SB_STAGE, acc, wm, wn, gID, tID, lane);
        if (s + 1 < NS) __syncthreads();
    }
    #pragma unroll
    for (int nt = 0; nt < 9; nt++){
        int cn = nb*144 + (wn + nt)*8 + 2*tID;
        if (cn >= PP) continue;
        float bb0 = (cn   < PCH) ? b1[cn]   : 0.f;
        float bb1 = (cn+1 < PCH) ? b1[cn+1] : 0.f;
        #pragma unroll
        for (int mt = 0; mt < 4; mt++){
            int row = mb + wm + mt*16 + gID;
            float2 v0, v1;
            v0.x = (cn   < PCH) ? to_tf32(fmaxf(acc[mt][nt][0] + bb0, 0.f)) : 0.f;
            v0.y = (cn+1 < PCH) ? to_tf32(fmaxf(acc[mt][nt][1] + bb1, 0.f)) : 0.f;
            v1.x = (cn   < PCH) ? to_tf32(fmaxf(acc[mt][nt][2] + bb0, 0.f)) : 0.f;
            v1.y = (cn+1 < PCH) ? to_tf32(fmaxf(acc[mt][nt][3] + bb1, 0.f)) : 0.f;
            *reinterpret_cast<float2*>(&g_h[(size_t)row*PP + cn])     = v0;
            *reinterpret_cast<float2*>(&g_h[(size_t)(row+8)*PP + cn]) = v1;
        }
    }
}

// ---------------- GEMM 3: upd = w2 @ h + emb[y]; out = x + mask*tanh(upd) ----------------
__global__ void __launch_bounds__(128) k_fc2(const float* __restrict__ x,
                                             const int*   __restrict__ y,
                                             const float* __restrict__ rmask,
                                             const float* __restrict__ emb,
                                             float*       __restrict__ out){
    __shared__ __align__(16) float sA[2*SA_STAGE];
    __shared__ __align__(16) float sB[2*SB_STAGE];
    const int tid = threadIdx.x;
    const int lane = tid & 31, warp = tid >> 5;
    const int gID = lane >> 2, tID = lane & 3;
    const int wm = (warp & 1) * 64, wn = (warp >> 1) * 9;
    const int mb = blockIdx.x * 128;

    const uint32_t sAb = (uint32_t)__cvta_generic_to_shared(sA);
    const uint32_t sBb = (uint32_t)__cvta_generic_to_shared(sB);
    const float* arow = g_h + (size_t)(mb + tid)*PP;

    auto loadA = [&](int s, int buf){
        uint32_t d = sAb + (uint32_t)(buf*SA_STAGE + tid*SA_STRIDE)*4;
        const float* src = arow + s*16;
        #pragma unroll
        for (int kc = 0; kc < 4; kc++) cpa(d + kc*16, src + kc*4, 16);
    };
    auto loadB = [&](int s, int buf){
        #pragma unroll
        for (int i = 0; i < 5; i++){
            int ci = i*128 + tid;
            if (ci < 576){
                int g = ci/288, r = ci - g*288;
                const float* src = g_w2f + ((size_t)((s*2 + g)*NT_FC2))*64 + r*4;
                cpa(sBb + (uint32_t)(buf*SB_STAGE + g*1152 + r*4)*4, src, 16);
            }
        }
    };

    float acc[4][9][4];
    #pragma unroll
    for (int i = 0; i < 4; i++) for (int j = 0; j < 9; j++) for (int q = 0; q < 4; q++) acc[i][j][q] = 0.f;

    loadA(0,0); loadB(0,0); cp_commit();
    const int NS = 26;
    for (int s = 0; s < NS; s++){
        if (s + 1 < NS){ loadA(s+1,(s+1)&1); loadB(s+1,(s+1)&1); cp_commit(); cp_wait<1>(); }
        else cp_wait<0>();
        __syncthreads();
        stage_compute(sA + (s&1)*SA_STAGE, sB + (s&1)*SB_STAGE, acc, wm, wn, gID, tID, lane);
        if (s + 1 < NS) __syncthreads();
    }

    const int yb = y[mb >> 15];                     // whole CTA = one batch element
    float msk[8];
    #pragma unroll
    for (int mt = 0; mt < 4; mt++)
        #pragma unroll
        for (int rr = 0; rr < 2; rr++){
            int row = mb + wm + mt*16 + gID + rr*8;
            float gv = x[(size_t)row*CCH];
            msk[mt*2+rr] = (rmask[row] <= 0.5f && gv > 0.1f) ? 1.f : 0.f;
            if ((warp >> 1) == 0 && tID == 0)
                out[(size_t)row*CCH] = gv;          // gray passthrough (unique writer)
        }

    #pragma unroll
    for (int nt = 0; nt < 9; nt++){
        int cn = (wn + nt)*8 + 2*tID;
        float e0 = (cn   < NO) ? emb[yb*NO + cn]     : 0.f;
        float e1 = (cn+1 < NO) ? emb[yb*NO + cn + 1] : 0.f;
        #pragma unroll
        for (int mt = 0; mt < 4; mt++)
            #pragma unroll
            for (int rr = 0; rr < 2; rr++){
                int row = mb + wm + mt*16 + gID + rr*8;
                float m = msk[mt*2+rr];
                float a0 = acc[mt][nt][rr*2+0] + e0;
                float a1 = acc[mt][nt][rr*2+1] + e1;
                if (cn < NO){
                    size_t o = (size_t)row*CCH + 1 + cn;
                    out[o] = x[o] + m*tanhf(a0);
                }
                if (cn + 1 < NO){
                    size_t o = (size_t)row*CCH + 2 + cn;
                    out[o] = x[o] + m*tanhf(a1);
                }
            }
    }
}

// ---------------- launch ----------------
extern "C" void kernel_launch(void* const* d_in, const int* in_sizes, int n_in,
                              void* d_out, int out_size) {
    const float* x     = (const float*)d_in[0];
    const int*   y     = (const int*)  d_in[1];
    const float* rmask = (const float*)d_in[2];
    const float* wp    = (const float*)d_in[3];
    const float* w1    = (const float*)d_in[4];
    const float* b1    = (const float*)d_in[5];
    const float* w2    = (const float*)d_in[6];
    const float* emb   = (const float*)d_in[7];
    float* out = (float*)d_out;

    k_prep_wc<<<(K8_CONV*NT_CONV*64 + 255)/256, 256>>>(wp);
    k_prep_w1<<<(K8_FC*NT_CONV*64 + 255)/256, 256>>>(w1);
    k_prep_w2<<<(K8_FC*NT_FC2*64 + 255)/256, 256>>>(w2);

    k_conv<<<dim3(1024, 3), 128>>>(x);
    k_fc1 <<<dim3(1024, 3), 128>>>(b1);
    k_fc2 <<<dim3(1024, 1), 128>>>(x, y, rmask, emb, out);
}

// round 4
// speedup vs baseline: 3.5607x; 1.0014x over previous
#include <cuda_runtime.h>
#include <math.h>
#include <stdint.h>

#define VOX   131072
#define CCH   136
#define PCH   408
#define PP    416          // padded P (13 * 32)
#define NO    135
#define NT_CONV 54         // padded n8-tiles for N=408 (3 blocks * 18)
#define NT_FC2  18
#define K8_CONV 120        // conv K = 952 padded to 960
#define K8_FC   52         // fc K = 408 padded to 416

#define SA_STRIDE 20       // 16 k-floats + 4 pad (conflict-free frag loads)
#define SA_STAGE  (128*SA_STRIDE)   // 2560 floats
#define SB_STAGE  (2*18*64)         // 2304 floats (2 k8-groups x 18 ntiles x 64)

// ---------------- scratch (device globals; no cudaMalloc allowed) ----------------
__device__ float g_p  [(size_t)VOX * PP];                 // conv out (relu, tf32-rounded)
__device__ float g_h  [(size_t)VOX * PP];                 // fc1 out (relu, tf32-rounded)
__device__ float g_wcf[(size_t)K8_CONV * NT_CONV * 64];   // conv W, fragment-major
__device__ float g_w1f[(size_t)K8_FC   * NT_CONV * 64];   // w1^T, fragment-major
__device__ float g_w2f[(size_t)K8_FC   * NT_FC2  * 64];   // w2^T, fragment-major

__constant__ int c_tap[7] = {4,10,12,13,14,16,22};
__constant__ int c_dz[7]  = {-1,0,0,0,0,0,1};
__constant__ int c_dy[7]  = {0,-1,0,0,0,1,0};
__constant__ int c_dx[7]  = {0,0,-1,0,1,0,0};

// ---------------- helpers ----------------
__device__ __forceinline__ float to_tf32(float x){
    uint32_t u; asm("cvt.rna.tf32.f32 %0, %1;" : "=r"(u) : "f"(x));
    return __uint_as_float(u);
}
__device__ __forceinline__ void mma_t(float* c, const uint32_t* a, uint32_t b0, uint32_t b1){
    asm volatile("mma.sync.aligned.m16n8k8.row.col.f32.tf32.tf32.f32 "
                 "{%0,%1,%2,%3}, {%4,%5,%6,%7}, {%8,%9}, {%0,%1,%2,%3};"
                 : "+f"(c[0]), "+f"(c[1]), "+f"(c[2]), "+f"(c[3])
                 : "r"(a[0]), "r"(a[1]), "r"(a[2]), "r"(a[3]), "r"(b0), "r"(b1));
}
__device__ __forceinline__ void cpa(uint32_t d, const void* s, int bytes){
    asm volatile("cp.async.cg.shared.global [%0], [%1], 16, %2;" :: "r"(d), "l"(s), "r"(bytes));
}
__device__ __forceinline__ void cp_commit(){ asm volatile("cp.async.commit_group;"); }
template<int N> __device__ __forceinline__ void cp_wait(){ asm volatile("cp.async.wait_group %0;" :: "n"(N)); }

// one K-stage (16 k) of warp-tile 64x72 compute.
// sA: [128][SA_STRIDE] row-major; sB: [2 k8][18 ntile][32 lane][2 slot].
__device__ __forceinline__ void stage_compute(const float* __restrict__ sA,
                                              const float* __restrict__ sB,
                                              float (&acc)[4][9][4],
                                              int wm, int wn, int gID, int tID, int lane){
    #pragma unroll
    for (int g8 = 0; g8 < 2; g8++){
        uint32_t a[4][4];
        #pragma unroll
        for (int mt = 0; mt < 4; mt++){
            const float* ap = sA + (wm + mt*16 + gID)*SA_STRIDE + g8*8 + tID;
            a[mt][0] = __float_as_uint(ap[0]);
            a[mt][1] = __float_as_uint(ap[8*SA_STRIDE]);
            a[mt][2] = __float_as_uint(ap[4]);
            a[mt][3] = __float_as_uint(ap[8*SA_STRIDE + 4]);
        }
        #pragma unroll
        for (int nt = 0; nt < 9; nt++){
            float2 bv = *reinterpret_cast<const float2*>(sB + (((g8*18) + wn + nt)*32 + lane)*2);
            uint32_t b0 = __float_as_uint(bv.x), b1 = __float_as_uint(bv.y);
            #pragma unroll
            for (int mt = 0; mt < 4; mt++)
                mma_t(acc[mt][nt], a[mt], b0, b1);
        }
    }
}

// ---------------- weight prep: pack fragment-major, tf32-rounded ----------------
__global__ void k_prep_wc(const float* __restrict__ wp){
    int i = blockIdx.x*256 + threadIdx.x;
    if (i >= K8_CONV*NT_CONV*64) return;
    int slot = i & 1, lane = (i>>1)&31, ntile = (i>>6)%NT_CONV, k8 = (i>>6)/NT_CONV;
    int kk = slot*4 + (lane&3);
    int k = k8*8 + kk, n = ntile*8 + (lane>>2);
    float v = 0.f;
    if (k < 952 && n < PCH){
        int off = k/136, c = k - off*136;
        v = to_tf32(wp[((size_t)n*CCH + c)*27 + c_tap[off]]);
    }
    g_wcf[i] = v;
}
__global__ void k_prep_w1(const float* __restrict__ w1){
    int i = blockIdx.x*256 + threadIdx.x;
    if (i >= K8_FC*NT_CONV*64) return;
    int slot = i & 1, lane = (i>>1)&31, ntile = (i>>6)%NT_CONV, k8 = (i>>6)/NT_CONV;
    int k = k8*8 + slot*4 + (lane&3), n = ntile*8 + (lane>>2);
    g_w1f[i] = (k < PCH && n < PCH) ? to_tf32(w1[(size_t)n*PCH + k]) : 0.f;
}
__global__ void k_prep_w2(const float* __restrict__ w2){
    int i = blockIdx.x*256 + threadIdx.x;
    if (i >= K8_FC*NT_FC2*64) return;
    int slot = i & 1, lane = (i>>1)&31, ntile = (i>>6)%NT_FC2, k8 = (i>>6)/NT_FC2;
    int k = k8*8 + slot*4 + (lane&3), n = ntile*8 + (lane>>2);
    g_w2f[i] = (k < PCH && n < NO) ? to_tf32(w2[(size_t)n*PCH + k]) : 0.f;
}

// ---------------- GEMM 1: conv (gathered A) + relu -> g_p ----------------
__global__ void __launch_bounds__(128) k_conv(const float* __restrict__ x){
    __shared__ __align__(16) float sA[2*SA_STAGE];
    __shared__ __align__(16) float sB[2*SB_STAGE];
    const int tid = threadIdx.x;
    const int lane = tid & 31, warp = tid >> 5;
    const int gID = lane >> 2, tID = lane & 3;
    const int wm = (warp & 1) * 64, wn = (warp >> 1) * 9;
    const int mb = blockIdx.x * 128;
    const int nb = blockIdx.y;

    // A-producer: this thread owns voxel row (mb+tid); precompute 7 neighbor ptrs
    const int vm = mb + tid;
    const int w0 = vm & 31, h0 = (vm >> 5) & 31, d0 = (vm >> 10) & 31, bb = vm >> 15;
    const float* nbr[7]; unsigned vmask = 0;
    #pragma unroll
    for (int o = 0; o < 7; o++){
        int dd = d0 + c_dz[o], hh = h0 + c_dy[o], ww = w0 + c_dx[o];
        bool v = ((((unsigned)dd) | ((unsigned)hh)) | ((unsigned)ww)) < 32u;
        nbr[o] = x + (v ? ((size_t)(((bb*32 + dd)*32 + hh)*32 + ww))*CCH : 0);
        if (v) vmask |= 1u << o;
    }
    const uint32_t sAb = (uint32_t)__cvta_generic_to_shared(sA);
    const uint32_t sBb = (uint32_t)__cvta_generic_to_shared(sB);

    auto loadA = [&](int s, int buf){
        uint32_t d = sAb + (uint32_t)(buf*SA_STAGE + tid*SA_STRIDE)*4;
        #pragma unroll
        for (int kc = 0; kc < 4; kc++){
            int k = s*16 + kc*4;
            int off = k/136, c = k - off*136;
            int ok = (off < 7) && ((vmask >> off) & 1);
            cpa(d + kc*16, nbr[off < 7 ? off : 0] + c, ok ? 16 : 0);
        }
    };
    auto loadB = [&](int s, int buf){
        #pragma unroll
        for (int i = 0; i < 5; i++){
            int ci = i*128 + tid;                 // 576 float4 per stage
            if (ci < 576){
                int g = ci/288, r = ci - g*288;
                const float* src = g_wcf + ((size_t)((s*2 + g)*NT_CONV + nb*18))*64 + r*4;
                cpa(sBb + (uint32_t)(buf*SB_STAGE + g*1152 + r*4)*4, src, 16);
            }
        }
    };

    float acc[4][9][4];
    #pragma unroll
    for (int i = 0; i < 4; i++) for (int j = 0; j < 9; j++) for (int q = 0; q < 4; q++) acc[i][j][q] = 0.f;

    loadA(0,0); loadB(0,0); cp_commit();
    const int NS = 60;                            // 120 k8 / 2 per stage
    for (int s = 0; s < NS; s++){
        if (s + 1 < NS){ loadA(s+1,(s+1)&1); loadB(s+1,(s+1)&1); cp_commit(); cp_wait<1>(); }
        else cp_wait<0>();
        __syncthreads();
        stage_compute(sA + (s&1)*SA_STAGE, sB + (s&1)*SB_STAGE, acc, wm, wn, gID, tID, lane);
        if (s + 1 < NS) __syncthreads();
    }
    #pragma unroll
    for (int nt = 0; nt < 9; nt++){
        int cn = nb*144 + (wn + nt)*8 + 2*tID;
        if (cn >= PP) continue;
        #pragma unroll
        for (int mt = 0; mt < 4; mt++){
            int row = mb + wm + mt*16 + gID;
            float2 v0, v1;
            v0.x = (cn   < PCH) ? to_tf32(fmaxf(acc[mt][nt][0], 0.f)) : 0.f;
            v0.y = (cn+1 < PCH) ? to_tf32(fmaxf(acc[mt][nt][1], 0.f)) : 0.f;
            v1.x = (cn   < PCH) ? to_tf32(fmaxf(acc[mt][nt][2], 0.f)) : 0.f;
            v1.y = (cn+1 < PCH) ? to_tf32(fmaxf(acc[mt][nt][3], 0.f)) : 0.f;
            *reinterpret_cast<float2*>(&g_p[(size_t)row*PP + cn])     = v0;
            *reinterpret_cast<float2*>(&g_p[(size_t)(row+8)*PP + cn]) = v1;
        }
    }
}

// ---------------- GEMM 2: h = relu(w1 @ p + b1) -> g_h ----------------
__global__ void __launch_bounds__(128) k_fc1(const float* __restrict__ b1){
    __shared__ __align__(16) float sA[2*SA_STAGE];
    __shared__ __align__(16) float sB[2*SB_STAGE];
    const int tid = threadIdx.x;
    const int lane = tid & 31, warp = tid >> 5;
    const int gID = lane >> 2, tID = lane & 3;
    const int wm = (warp & 1) * 64, wn = (warp >> 1) * 9;
    const int mb = blockIdx.x * 128;
    const int nb = blockIdx.y;

    const uint32_t sAb = (uint32_t)__cvta_generic_to_shared(sA);
    const uint32_t sBb = (uint32_t)__cvta_generic_to_shared(sB);
    const float* arow = g_p + (size_t)(mb + tid)*PP;

    auto loadA = [&](int s, int buf){
        uint32_t d = sAb + (uint32_t)(buf*SA_STAGE + tid*SA_STRIDE)*4;
        const float* src = arow + s*16;
        #pragma unroll
        for (int kc = 0; kc < 4; kc++) cpa(d + kc*16, src + kc*4, 16);
    };
    auto loadB = [&](int s, int buf){
        #pragma unroll
        for (int i = 0; i < 5; i++){
            int ci = i*128 + tid;
            if (ci < 576){
                int g = ci/288, r = ci - g*288;
                const float* src = g_w1f + ((size_t)((s*2 + g)*NT_CONV + nb*18))*64 + r*4;
                cpa(sBb + (uint32_t)(buf*SB_STAGE + g*1152 + r*4)*4, src, 16);
            }
        }
    };

    float acc[4][9][4];
    #pragma unroll
    for (int i = 0; i < 4; i++) for (int j = 0; j < 9; j++) for (int q = 0; q < 4; q++) acc[i][j][q] = 0.f;

    loadA(0,0); loadB(0,0); cp_commit();
    const int NS = 26;                            // 52 k8 / 2
    for (int s = 0; s < NS; s++){
        if (s + 1 < NS){ loadA(s+1,(s+1)&1); loadB(s+1,(s+1)&1); cp_commit(); cp_wait<1>(); }
        else cp_wait<0>();
        __syncthreads();
        stage_compute(sA + (s&1)*SA_STAGE, sB + (s&1)*SB_STAGE, acc, wm, wn, gID, tID, lane);
        if (s + 1 < NS) __syncthreads();
    }
    #pragma unroll
    for (int nt = 0; nt < 9; nt++){
        int cn = nb*144 + (wn + nt)*8 + 2*tID;
        if (cn >= PP) continue;
        float bb0 = (cn   < PCH) ? b1[cn]   : 0.f;
        float bb1 = (cn+1 < PCH) ? b1[cn+1] : 0.f;
        #pragma unroll
        for (int mt = 0; mt < 4; mt++){
            int row = mb + wm + mt*16 + gID;
            float2 v0, v1;
            v0.x = (cn   < PCH) ? to_tf32(fmaxf(acc[mt][nt][0] + bb0, 0.f)) : 0.f;
            v0.y = (cn+1 < PCH) ? to_tf32(fmaxf(acc[mt][nt][1] + bb1, 0.f)) : 0.f;
            v1.x = (cn   < PCH) ? to_tf32(fmaxf(acc[mt][nt][2] + bb0, 0.f)) : 0.f;
            v1.y = (cn+1 < PCH) ? to_tf32(fmaxf(acc[mt][nt][3] + bb1, 0.f)) : 0.f;
            *reinterpret_cast<float2*>(&g_h[(size_t)row*PP + cn])     = v0;
            *reinterpret_cast<float2*>(&g_h[(size_t)(row+8)*PP + cn]) = v1;
        }
    }
}

// ---------------- GEMM 3: upd = w2 @ h + emb[y]; out = x + mask*tanh(upd) ----------------
__global__ void __launch_bounds__(128) k_fc2(const float* __restrict__ x,
                                             const int*   __restrict__ y,
                                             const float* __restrict__ rmask,
                                             const float* __restrict__ emb,
                                             float*       __restrict__ out){
    __shared__ __align__(16) float sA[2*SA_STAGE];
    __shared__ __align__(16) float sB[2*SB_STAGE];
    const int tid = threadIdx.x;
    const int lane = tid & 31, warp = tid >> 5;
    const int gID = lane >> 2, tID = lane & 3;
    const int wm = (warp & 1) * 64, wn = (warp >> 1) * 9;
    const int mb = blockIdx.x * 128;

    const uint32_t sAb = (uint32_t)__cvta_generic_to_shared(sA);
    const uint32_t sBb = (uint32_t)__cvta_generic_to_shared(sB);
    const float* arow = g_h + (size_t)(mb + tid)*PP;

    auto loadA = [&](int s, int buf){
        uint32_t d = sAb + (uint32_t)(buf*SA_STAGE + tid*SA_STRIDE)*4;
        const float* src = arow + s*16;
        #pragma unroll
        for (int kc = 0; kc < 4; kc++) cpa(d + kc*16, src + kc*4, 16);
    };
    auto loadB = [&](int s, int buf){
        #pragma unroll
        for (int i = 0; i < 5; i++){
            int ci = i*128 + tid;
            if (ci < 576){
                int g = ci/288, r = ci - g*288;
                const float* src = g_w2f + ((size_t)((s*2 + g)*NT_FC2))*64 + r*4;
                cpa(sBb + (uint32_t)(buf*SB_STAGE + g*1152 + r*4)*4, src, 16);
            }
        }
    };

    float acc[4][9][4];
    #pragma unroll
    for (int i = 0; i < 4; i++) for (int j = 0; j < 9; j++) for (int q = 0; q < 4; q++) acc[i][j][q] = 0.f;

    loadA(0,0); loadB(0,0); cp_commit();
    const int NS = 26;
    for (int s = 0; s < NS; s++){
        if (s + 1 < NS){ loadA(s+1,(s+1)&1); loadB(s+1,(s+1)&1); cp_commit(); cp_wait<1>(); }
        else cp_wait<0>();
        __syncthreads();
        stage_compute(sA + (s&1)*SA_STAGE, sB + (s&1)*SB_STAGE, acc, wm, wn, gID, tID, lane);
        if (s + 1 < NS) __syncthreads();
    }

    const int yb = y[mb >> 15];                     // whole CTA = one batch element
    float msk[8];
    #pragma unroll
    for (int mt = 0; mt < 4; mt++)
        #pragma unroll
        for (int rr = 0; rr < 2; rr++){
            int row = mb + wm + mt*16 + gID + rr*8;
            float gv = x[(size_t)row*CCH];
            msk[mt*2+rr] = (rmask[row] <= 0.5f && gv > 0.1f) ? 1.f : 0.f;
            if ((warp >> 1) == 0 && tID == 0)
                out[(size_t)row*CCH] = gv;          // gray passthrough (unique writer)
        }

    #pragma unroll
    for (int nt = 0; nt < 9; nt++){
        int cn = (wn + nt)*8 + 2*tID;
        float e0 = (cn   < NO) ? emb[yb*NO + cn]     : 0.f;
        float e1 = (cn+1 < NO) ? emb[yb*NO + cn + 1] : 0.f;
        #pragma unroll
        for (int mt = 0; mt < 4; mt++)
            #pragma unroll
            for (int rr = 0; rr < 2; rr++){
                int row = mb + wm + mt*16 + gID + rr*8;
                float m = msk[mt*2+rr];
                float a0 = acc[mt][nt][rr*2+0] + e0;
                float a1 = acc[mt][nt][rr*2+1] + e1;
                if (cn < NO){
                    size_t o = (size_t)row*CCH + 1 + cn;
                    out[o] = x[o] + m*tanhf(a0);
                }
                if (cn + 1 < NO){
                    size_t o = (size_t)row*CCH + 2 + cn;
                    out[o] = x[o] + m*tanhf(a1);
                }
            }
    }
}

// ---------------- launch ----------------
extern "C" void kernel_launch(void* const* d_in, const int* in_sizes, int n_in,
                              void* d_out, int out_size) {
    const float* x     = (const float*)d_in[0];
    const int*   y     = (const int*)  d_in[1];
    const float* rmask = (const float*)d_in[2];
    const float* wp    = (const float*)d_in[3];
    const float* w1    = (const float*)d_in[4];
    const float* b1    = (const float*)d_in[5];
    const float* w2    = (const float*)d_in[6];
    const float* emb   = (const float*)d_in[7];
    float* out = (float*)d_out;

    k_prep_wc<<<(K8_CONV*NT_CONV*64 + 255)/256, 256>>>(wp);
    k_prep_w1<<<(K8_FC*NT_CONV*64 + 255)/256, 256>>>(w1);
    k_prep_w2<<<(K8_FC*NT_FC2*64 + 255)/256, 256>>>(w2);

    k_conv<<<dim3(1024, 3), 128>>>(x);
    k_fc1 <<<dim3(1024, 3), 128>>>(b1);
    k_fc2 <<<dim3(1024, 1), 128>>>(x, y, rmask, emb, out);
}

// round 5
// speedup vs baseline: 3.5668x; 1.0017x over previous
#include <cuda_runtime.h>
#include <math.h>
#include <stdint.h>

#define VOX   131072
#define CCH   136
#define PCH   408
#define PP    416          // padded P (13 * 32)
#define NO    135
#define NT_CONV 54         // padded n8-tiles for N=408 (3 blocks * 18)
#define NT_FC2  18
#define K8_CONV 120        // conv K = 952 padded to 960
#define K8_FC   52         // fc K = 408 padded to 416

#define SA_STRIDE 20       // 16 k-floats + 4 pad (conflict-free frag loads)
#define SA_STAGE  (128*SA_STRIDE)   // 2560 floats
#define SB_STAGE  (2*18*64)         // 2304 floats (2 k8-groups x 18 ntiles x 64)

// ---------------- scratch (device globals; no cudaMalloc allowed) ----------------
__device__ float g_p  [(size_t)VOX * PP];                 // conv out (relu, tf32-rounded)
__device__ float g_h  [(size_t)VOX * PP];                 // fc1 out (relu, tf32-rounded)
__device__ float g_wcf[(size_t)K8_CONV * NT_CONV * 64];   // conv W, fragment-major
__device__ float g_w1f[(size_t)K8_FC   * NT_CONV * 64];   // w1^T, fragment-major
__device__ float g_w2f[(size_t)K8_FC   * NT_FC2  * 64];   // w2^T, fragment-major

__constant__ int c_tap[7] = {4,10,12,13,14,16,22};
__constant__ int c_dz[7]  = {-1,0,0,0,0,0,1};
__constant__ int c_dy[7]  = {0,-1,0,0,0,1,0};
__constant__ int c_dx[7]  = {0,0,-1,0,1,0,0};

// ---------------- helpers ----------------
__device__ __forceinline__ float to_tf32(float x){
    uint32_t u; asm("cvt.rna.tf32.f32 %0, %1;" : "=r"(u) : "f"(x));
    return __uint_as_float(u);
}
__device__ __forceinline__ void mma_t(float* c, const uint32_t* a, uint32_t b0, uint32_t b1){
    asm volatile("mma.sync.aligned.m16n8k8.row.col.f32.tf32.tf32.f32 "
                 "{%0,%1,%2,%3}, {%4,%5,%6,%7}, {%8,%9}, {%0,%1,%2,%3};"
                 : "+f"(c[0]), "+f"(c[1]), "+f"(c[2]), "+f"(c[3])
                 : "r"(a[0]), "r"(a[1]), "r"(a[2]), "r"(a[3]), "r"(b0), "r"(b1));
}
__device__ __forceinline__ void cpa(uint32_t d, const void* s, int bytes){
    asm volatile("cp.async.cg.shared.global [%0], [%1], 16, %2;" :: "r"(d), "l"(s), "r"(bytes));
}
__device__ __forceinline__ void cp_commit(){ asm volatile("cp.async.commit_group;"); }
template<int N> __device__ __forceinline__ void cp_wait(){ asm volatile("cp.async.wait_group %0;" :: "n"(N)); }

// one K-stage (16 k) of warp-tile 64x72 compute.
// sA: [128][SA_STRIDE] row-major; sB: [2 k8][18 ntile][32 lane][2 slot].
__device__ __forceinline__ void stage_compute(const float* __restrict__ sA,
                                              const float* __restrict__ sB,
                                              float (&acc)[4][9][4],
                                              int wm, int wn, int gID, int tID, int lane){
    #pragma unroll
    for (int g8 = 0; g8 < 2; g8++){
        uint32_t a[4][4];
        #pragma unroll
        for (int mt = 0; mt < 4; mt++){
            const float* ap = sA + (wm + mt*16 + gID)*SA_STRIDE + g8*8 + tID;
            a[mt][0] = __float_as_uint(ap[0]);
            a[mt][1] = __float_as_uint(ap[8*SA_STRIDE]);
            a[mt][2] = __float_as_uint(ap[4]);
            a[mt][3] = __float_as_uint(ap[8*SA_STRIDE + 4]);
        }
        #pragma unroll
        for (int nt = 0; nt < 9; nt++){
            float2 bv = *reinterpret_cast<const float2*>(sB + (((g8*18) + wn + nt)*32 + lane)*2);
            uint32_t b0 = __float_as_uint(bv.x), b1 = __float_as_uint(bv.y);
            #pragma unroll
            for (int mt = 0; mt < 4; mt++)
                mma_t(acc[mt][nt], a[mt], b0, b1);
        }
    }
}

// ---------------- weight prep: pack fragment-major, tf32-rounded ----------------
__global__ void k_prep_wc(const float* __restrict__ wp){
    int i = blockIdx.x*256 + threadIdx.x;
    if (i >= K8_CONV*NT_CONV*64) return;
    int slot = i & 1, lane = (i>>1)&31, ntile = (i>>6)%NT_CONV, k8 = (i>>6)/NT_CONV;
    int kk = slot*4 + (lane&3);
    int k = k8*8 + kk, n = ntile*8 + (lane>>2);
    float v = 0.f;
    if (k < 952 && n < PCH){
        int off = k/136, c = k - off*136;
        v = to_tf32(wp[((size_t)n*CCH + c)*27 + c_tap[off]]);
    }
    g_wcf[i] = v;
}
__global__ void k_prep_w1(const float* __restrict__ w1){
    int i = blockIdx.x*256 + threadIdx.x;
    if (i >= K8_FC*NT_CONV*64) return;
    int slot = i & 1, lane = (i>>1)&31, ntile = (i>>6)%NT_CONV, k8 = (i>>6)/NT_CONV;
    int k = k8*8 + slot*4 + (lane&3), n = ntile*8 + (lane>>2);
    g_w1f[i] = (k < PCH && n < PCH) ? to_tf32(w1[(size_t)n*PCH + k]) : 0.f;
}
__global__ void k_prep_w2(const float* __restrict__ w2){
    int i = blockIdx.x*256 + threadIdx.x;
    if (i >= K8_FC*NT_FC2*64) return;
    int slot = i & 1, lane = (i>>1)&31, ntile = (i>>6)%NT_FC2, k8 = (i>>6)/NT_FC2;
    int k = k8*8 + slot*4 + (lane&3), n = ntile*8 + (lane>>2);
    g_w2f[i] = (k < PCH && n < NO) ? to_tf32(w2[(size_t)n*PCH + k]) : 0.f;
}

// ---------------- GEMM 1: conv (gathered A) + relu -> g_p ----------------
__global__ void __launch_bounds__(128) k_conv(const float* __restrict__ x){
    __shared__ __align__(16) float sA[2*SA_STAGE];
    __shared__ __align__(16) float sB[2*SB_STAGE];
    const int tid = threadIdx.x;
    const int lane = tid & 31, warp = tid >> 5;
    const int gID = lane >> 2, tID = lane & 3;
    const int wm = (warp & 1) * 64, wn = (warp >> 1) * 9;
    const int mb = blockIdx.x * 128;
    const int nb = blockIdx.y;

    // A-producer: this thread owns voxel row (mb+tid); precompute 7 neighbor ptrs
    const int vm = mb + tid;
    const int w0 = vm & 31, h0 = (vm >> 5) & 31, d0 = (vm >> 10) & 31, bb = vm >> 15;
    const float* nbr[7]; unsigned vmask = 0;
    #pragma unroll
    for (int o = 0; o < 7; o++){
        int dd = d0 + c_dz[o], hh = h0 + c_dy[o], ww = w0 + c_dx[o];
        bool v = ((((unsigned)dd) | ((unsigned)hh)) | ((unsigned)ww)) < 32u;
        nbr[o] = x + (v ? ((size_t)(((bb*32 + dd)*32 + hh)*32 + ww))*CCH : 0);
        if (v) vmask |= 1u << o;
    }
    const uint32_t sAb = (uint32_t)__cvta_generic_to_shared(sA);
    const uint32_t sBb = (uint32_t)__cvta_generic_to_shared(sB);

    auto loadA = [&](int s, int buf){
        uint32_t d = sAb + (uint32_t)(buf*SA_STAGE + tid*SA_STRIDE)*4;
        #pragma unroll
        for (int kc = 0; kc < 4; kc++){
            int k = s*16 + kc*4;
            int off = k/136, c = k - off*136;
            int ok = (off < 7) && ((vmask >> off) & 1);
            cpa(d + kc*16, nbr[off < 7 ? off : 0] + c, ok ? 16 : 0);
        }
    };
    auto loadB = [&](int s, int buf){
        #pragma unroll
        for (int i = 0; i < 5; i++){
            int ci = i*128 + tid;                 // 576 float4 per stage
            if (ci < 576){
                int g = ci/288, r = ci - g*288;
                const float* src = g_wcf + ((size_t)((s*2 + g)*NT_CONV + nb*18))*64 + r*4;
                cpa(sBb + (uint32_t)(buf*SB_STAGE + g*1152 + r*4)*4, src, 16);
            }
        }
    };

    float acc[4][9][4];
    #pragma unroll
    for (int i = 0; i < 4; i++) for (int j = 0; j < 9; j++) for (int q = 0; q < 4; q++) acc[i][j][q] = 0.f;

    loadA(0,0); loadB(0,0); cp_commit();
    const int NS = 60;                            // 120 k8 / 2 per stage
    for (int s = 0; s < NS; s++){
        if (s + 1 < NS){ loadA(s+1,(s+1)&1); loadB(s+1,(s+1)&1); cp_commit(); cp_wait<1>(); }
        else cp_wait<0>();
        __syncthreads();
        stage_compute(sA + (s&1)*SA_STAGE, sB + (s&1)*SB_STAGE, acc, wm, wn, gID, tID, lane);
        if (s + 1 < NS) __syncthreads();
    }
    #pragma unroll
    for (int nt = 0; nt < 9; nt++){
        int cn = nb*144 + (wn + nt)*8 + 2*tID;
        if (cn >= PP) continue;
        #pragma unroll
        for (int mt = 0; mt < 4; mt++){
            int row = mb + wm + mt*16 + gID;
            float2 v0, v1;
            v0.x = (cn   < PCH) ? to_tf32(fmaxf(acc[mt][nt][0], 0.f)) : 0.f;
            v0.y = (cn+1 < PCH) ? to_tf32(fmaxf(acc[mt][nt][1], 0.f)) : 0.f;
            v1.x = (cn   < PCH) ? to_tf32(fmaxf(acc[mt][nt][2], 0.f)) : 0.f;
            v1.y = (cn+1 < PCH) ? to_tf32(fmaxf(acc[mt][nt][3], 0.f)) : 0.f;
            *reinterpret_cast<float2*>(&g_p[(size_t)row*PP + cn])     = v0;
            *reinterpret_cast<float2*>(&g_p[(size_t)(row+8)*PP + cn]) = v1;
        }
    }
}

// ---------------- GEMM 2: h = relu(w1 @ p + b1) -> g_h ----------------
__global__ void __launch_bounds__(128) k_fc1(const float* __restrict__ b1){
    __shared__ __align__(16) float sA[2*SA_STAGE];
    __shared__ __align__(16) float sB[2*SB_STAGE];
    const int tid = threadIdx.x;
    const int lane = tid & 31, warp = tid >> 5;
    const int gID = lane >> 2, tID = lane & 3;
    const int wm = (warp & 1) * 64, wn = (warp >> 1) * 9;
    const int mb = blockIdx.x * 128;
    const int nb = blockIdx.y;

    const uint32_t sAb = (uint32_t)__cvta_generic_to_shared(sA);
    const uint32_t sBb = (uint32_t)__cvta_generic_to_shared(sB);
    const float* arow = g_p + (size_t)(mb + tid)*PP;

    auto loadA = [&](int s, int buf){
        uint32_t d = sAb + (uint32_t)(buf*SA_STAGE + tid*SA_STRIDE)*4;
        const float* src = arow + s*16;
        #pragma unroll
        for (int kc = 0; kc < 4; kc++) cpa(d + kc*16, src + kc*4, 16);
    };
    auto loadB = [&](int s, int buf){
        #pragma unroll
        for (int i = 0; i < 5; i++){
            int ci = i*128 + tid;
            if (ci < 576){
                int g = ci/288, r = ci - g*288;
                const float* src = g_w1f + ((size_t)((s*2 + g)*NT_CONV + nb*18))*64 + r*4;
                cpa(sBb + (uint32_t)(buf*SB_STAGE + g*1152 + r*4)*4, src, 16);
            }
        }
    };

    float acc[4][9][4];
    #pragma unroll
    for (int i = 0; i < 4; i++) for (int j = 0; j < 9; j++) for (int q = 0; q < 4; q++) acc[i][j][q] = 0.f;

    loadA(0,0); loadB(0,0); cp_commit();
    const int NS = 26;                            // 52 k8 / 2
    for (int s = 0; s < NS; s++){
        if (s + 1 < NS){ loadA(s+1,(s+1)&1); loadB(s+1,(s+1)&1); cp_commit(); cp_wait<1>(); }
        else cp_wait<0>();
        __syncthreads();
        stage_compute(sA + (s&1)*SA_STAGE, sB + (s&1)*SB_STAGE, acc, wm, wn, gID, tID, lane);
        if (s + 1 < NS) __syncthreads();
    }
    #pragma unroll
    for (int nt = 0; nt < 9; nt++){
        int cn = nb*144 + (wn + nt)*8 + 2*tID;
        if (cn >= PP) continue;
        float bb0 = (cn   < PCH) ? b1[cn]   : 0.f;
        float bb1 = (cn+1 < PCH) ? b1[cn+1] : 0.f;
        #pragma unroll
        for (int mt = 0; mt < 4; mt++){
            int row = mb + wm + mt*16 + gID;
            float2 v0, v1;
            v0.x = (cn   < PCH) ? to_tf32(fmaxf(acc[mt][nt][0] + bb0, 0.f)) : 0.f;
            v0.y = (cn+1 < PCH) ? to_tf32(fmaxf(acc[mt][nt][1] + bb1, 0.f)) : 0.f;
            v1.x = (cn   < PCH) ? to_tf32(fmaxf(acc[mt][nt][2] + bb0, 0.f)) : 0.f;
            v1.y = (cn+1 < PCH) ? to_tf32(fmaxf(acc[mt][nt][3] + bb1, 0.f)) : 0.f;
            *reinterpret_cast<float2*>(&g_h[(size_t)row*PP + cn])     = v0;
            *reinterpret_cast<float2*>(&g_h[(size_t)(row+8)*PP + cn]) = v1;
        }
    }
}

// ---------------- GEMM 3: upd = w2 @ h + emb[y]; out = x + mask*tanh(upd) ----------------
__global__ void __launch_bounds__(128) k_fc2(const float* __restrict__ x,
                                             const int*   __restrict__ y,
                                             const float* __restrict__ rmask,
                                             const float* __restrict__ emb,
                                             float*       __restrict__ out){
    __shared__ __align__(16) float sA[2*SA_STAGE];
    __shared__ __align__(16) float sB[2*SB_STAGE];
    const int tid = threadIdx.x;
    const int lane = tid & 31, warp = tid >> 5;
    const int gID = lane >> 2, tID = lane & 3;
    const int wm = (warp & 1) * 64, wn = (warp >> 1) * 9;
    const int mb = blockIdx.x * 128;

    const uint32_t sAb = (uint32_t)__cvta_generic_to_shared(sA);
    const uint32_t sBb = (uint32_t)__cvta_generic_to_shared(sB);
    const float* arow = g_h + (size_t)(mb + tid)*PP;

    auto loadA = [&](int s, int buf){
        uint32_t d = sAb + (uint32_t)(buf*SA_STAGE + tid*SA_STRIDE)*4;
        const float* src = arow + s*16;
        #pragma unroll
        for (int kc = 0; kc < 4; kc++) cpa(d + kc*16, src + kc*4, 16);
    };
    auto loadB = [&](int s, int buf){
        #pragma unroll
        for (int i = 0; i < 5; i++){
            int ci = i*128 + tid;
            if (ci < 576){
                int g = ci/288, r = ci - g*288;
                const float* src = g_w2f + ((size_t)((s*2 + g)*NT_FC2))*64 + r*4;
                cpa(sBb + (uint32_t)(buf*SB_STAGE + g*1152 + r*4)*4, src, 16);
            }
        }
    };

    float acc[4][9][4];
    #pragma unroll
    for (int i = 0; i < 4; i++) for (int j = 0; j < 9; j++) for (int q = 0; q < 4; q++) acc[i][j][q] = 0.f;

    loadA(0,0); loadB(0,0); cp_commit();
    const int NS = 26;
    for (int s = 0; s < NS; s++){
        if (s + 1 < NS){ loadA(s+1,(s+1)&1); loadB(s+1,(s+1)&1); cp_commit(); cp_wait<1>(); }
        else cp_wait<0>();
        __syncthreads();
        stage_compute(sA + (s&1)*SA_STAGE, sB + (s&1)*SB_STAGE, acc, wm, wn, gID, tID, lane);
        if (s + 1 < NS) __syncthreads();
    }

    const int yb = y[mb >> 15];                     // whole CTA = one batch element
    float msk[8];
    #pragma unroll
    for (int mt = 0; mt < 4; mt++)
        #pragma unroll
        for (int rr = 0; rr < 2; rr++){
            int row = mb + wm + mt*16 + gID + rr*8;
            float gv = x[(size_t)row*CCH];
            msk[mt*2+rr] = (rmask[row] <= 0.5f && gv > 0.1f) ? 1.f : 0.f;
            if ((warp >> 1) == 0 && tID == 0)
                out[(size_t)row*CCH] = gv;          // gray passthrough (unique writer)
        }

    #pragma unroll
    for (int nt = 0; nt < 9; nt++){
        int cn = (wn + nt)*8 + 2*tID;
        float e0 = (cn   < NO) ? emb[yb*NO + cn]     : 0.f;
        float e1 = (cn+1 < NO) ? emb[yb*NO + cn + 1] : 0.f;
        #pragma unroll
        for (int mt = 0; mt < 4; mt++)
            #pragma unroll
            for (int rr = 0; rr < 2; rr++){
                int row = mb + wm + mt*16 + gID + rr*8;
                float m = msk[mt*2+rr];
                float a0 = acc[mt][nt][rr*2+0] + e0;
                float a1 = acc[mt][nt][rr*2+1] + e1;
                if (cn < NO){
                    size_t o = (size_t)row*CCH + 1 + cn;
                    out[o] = x[o] + m*tanhf(a0);
                }
                if (cn + 1 < NO){
                    size_t o = (size_t)row*CCH + 2 + cn;
                    out[o] = x[o] + m*tanhf(a1);
                }
            }
    }
}

// ---------------- launch ----------------
extern "C" void kernel_launch(void* const* d_in, const int* in_sizes, int n_in,
                              void* d_out, int out_size) {
    const float* x     = (const float*)d_in[0];
    const int*   y     = (const int*)  d_in[1];
    const float* rmask = (const float*)d_in[2];
    const float* wp    = (const float*)d_in[3];
    const float* w1    = (const float*)d_in[4];
    const float* b1    = (const float*)d_in[5];
    const float* w2    = (const float*)d_in[6];
    const float* emb   = (const float*)d_in[7];
    float* out = (float*)d_out;

    k_prep_wc<<<(K8_CONV*NT_CONV*64 + 255)/256, 256>>>(wp);
    k_prep_w1<<<(K8_FC*NT_CONV*64 + 255)/256, 256>>>(w1);
    k_prep_w2<<<(K8_FC*NT_FC2*64 + 255)/256, 256>>>(w2);

    k_conv<<<dim3(1024, 3), 128>>>(x);
    k_fc1 <<<dim3(1024, 3), 128>>>(b1);
    k_fc2 <<<dim3(1024, 1), 128>>>(x, y, rmask, emb, out);
}